// round 2
// baseline (speedup 1.0000x reference)
#include <cuda_runtime.h>

// Problem constants (fixed shapes from reference)
#define BATCH   4
#define SEQ     2048
#define DMODEL  1024
#define HEADS   16
#define HDIM    64
#define MTOT    (BATCH*SEQ)      // 8192
#define LDP     68               // padded smem row stride for flash tiles

// Scratch (no cudaMalloc allowed) — 4 x 32MB fp32 buffers
__device__ float g_q[MTOT * DMODEL];
__device__ float g_k[MTOT * DMODEL];
__device__ float g_v[MTOT * DMODEL];
__device__ float g_ctx[MTOT * DMODEL];

// ---------------------------------------------------------------------------
// Tiled GEMM 128x128x8, 256 threads, 8x8 per-thread tile, double-buffered smem
// C[M=8192, N=1024] = A[M,K=1024] @ W[K,N=1024]
// epi: QKV permuted store (out[b,h,s,d]) selected by blockIdx.z
// ---------------------------------------------------------------------------
__global__ __launch_bounds__(256, 2) void qkv_gemm_kernel(
    const float* __restrict__ x,
    const float* __restrict__ Wq,
    const float* __restrict__ Wk,
    const float* __restrict__ Wv)
{
    const int K = DMODEL, N = DMODEL;
    const float* __restrict__ W = (blockIdx.z == 0) ? Wq : (blockIdx.z == 1) ? Wk : Wv;
    float* __restrict__ out = (blockIdx.z == 0) ? g_q : (blockIdx.z == 1) ? g_k : g_v;

    __shared__ float As[2][8][128];
    __shared__ float Bs[2][8][128];

    const int tid = threadIdx.x;
    const int m0 = blockIdx.y * 128;
    const int n0 = blockIdx.x * 128;

    const int arow = tid >> 1;          // 0..127
    const int acol = (tid & 1) << 2;    // 0 or 4
    const int brow = tid >> 5;          // 0..7
    const int bcol = (tid & 31) << 2;   // 0..124

    const float* Aptr = x + (size_t)(m0 + arow) * K + acol;
    const float* Bptr = W + (size_t)brow * N + n0 + bcol;

    float4 ga = *(const float4*)Aptr;
    float4 gb = *(const float4*)Bptr;
    As[0][acol + 0][arow] = ga.x;
    As[0][acol + 1][arow] = ga.y;
    As[0][acol + 2][arow] = ga.z;
    As[0][acol + 3][arow] = ga.w;
    *(float4*)&Bs[0][brow][bcol] = gb;
    __syncthreads();

    const int tx = tid & 15;
    const int ty = tid >> 4;

    float acc[8][8];
#pragma unroll
    for (int i = 0; i < 8; i++)
#pragma unroll
        for (int j = 0; j < 8; j++) acc[i][j] = 0.f;

    const int NT = K / 8;  // 128
    for (int t = 0; t < NT; t++) {
        const int cb = t & 1;
        const int nb = (t + 1) & 1;
        if (t + 1 < NT) {
            ga = *(const float4*)(Aptr + (t + 1) * 8);
            gb = *(const float4*)(Bptr + (size_t)(t + 1) * 8 * N);
        }
#pragma unroll
        for (int k = 0; k < 8; k++) {
            float a[8], b[8];
            *(float4*)&a[0] = *(const float4*)&As[cb][k][ty * 4];
            *(float4*)&a[4] = *(const float4*)&As[cb][k][64 + ty * 4];
            *(float4*)&b[0] = *(const float4*)&Bs[cb][k][tx * 4];
            *(float4*)&b[4] = *(const float4*)&Bs[cb][k][64 + tx * 4];
#pragma unroll
            for (int i = 0; i < 8; i++)
#pragma unroll
                for (int j = 0; j < 8; j++)
                    acc[i][j] = fmaf(a[i], b[j], acc[i][j]);
        }
        if (t + 1 < NT) {
            As[nb][acol + 0][arow] = ga.x;
            As[nb][acol + 1][arow] = ga.y;
            As[nb][acol + 2][arow] = ga.z;
            As[nb][acol + 3][arow] = ga.w;
            *(float4*)&Bs[nb][brow][bcol] = gb;
        }
        __syncthreads();
    }

    // Permuted epilogue: (m, n) -> out[((b*H + h)*S + s)*64 + d]
#pragma unroll
    for (int i = 0; i < 8; i++) {
        const int ml = (i < 4) ? (ty * 4 + i) : (64 + ty * 4 + (i - 4));
        const int m = m0 + ml;
        const int bb = m >> 11;           // m / SEQ
        const int ss = m & (SEQ - 1);
#pragma unroll
        for (int jj = 0; jj < 2; jj++) {
            const int n = n0 + (jj ? (64 + tx * 4) : (tx * 4));
            const int h = n >> 6;
            const int d = n & 63;
            float4 v = make_float4(acc[i][jj * 4 + 0], acc[i][jj * 4 + 1],
                                   acc[i][jj * 4 + 2], acc[i][jj * 4 + 3]);
            *(float4*)&out[((size_t)((bb << 4) + h) * SEQ + ss) * HDIM + d] = v;
        }
    }
}

// ---------------------------------------------------------------------------
// Output projection: out = ctx @ Wo + bo   (plain layout)
// ---------------------------------------------------------------------------
__global__ __launch_bounds__(256, 2) void oproj_gemm_kernel(
    const float* __restrict__ Wo,
    const float* __restrict__ bo,
    float* __restrict__ out)
{
    const int K = DMODEL, N = DMODEL;
    const float* __restrict__ A = g_ctx;

    __shared__ float As[2][8][128];
    __shared__ float Bs[2][8][128];

    const int tid = threadIdx.x;
    const int m0 = blockIdx.y * 128;
    const int n0 = blockIdx.x * 128;

    const int arow = tid >> 1;
    const int acol = (tid & 1) << 2;
    const int brow = tid >> 5;
    const int bcol = (tid & 31) << 2;

    const float* Aptr = A + (size_t)(m0 + arow) * K + acol;
    const float* Bptr = Wo + (size_t)brow * N + n0 + bcol;

    float4 ga = *(const float4*)Aptr;
    float4 gb = *(const float4*)Bptr;
    As[0][acol + 0][arow] = ga.x;
    As[0][acol + 1][arow] = ga.y;
    As[0][acol + 2][arow] = ga.z;
    As[0][acol + 3][arow] = ga.w;
    *(float4*)&Bs[0][brow][bcol] = gb;
    __syncthreads();

    const int tx = tid & 15;
    const int ty = tid >> 4;

    float acc[8][8];
#pragma unroll
    for (int i = 0; i < 8; i++)
#pragma unroll
        for (int j = 0; j < 8; j++) acc[i][j] = 0.f;

    const int NT = K / 8;
    for (int t = 0; t < NT; t++) {
        const int cb = t & 1;
        const int nb = (t + 1) & 1;
        if (t + 1 < NT) {
            ga = *(const float4*)(Aptr + (t + 1) * 8);
            gb = *(const float4*)(Bptr + (size_t)(t + 1) * 8 * N);
        }
#pragma unroll
        for (int k = 0; k < 8; k++) {
            float a[8], b[8];
            *(float4*)&a[0] = *(const float4*)&As[cb][k][ty * 4];
            *(float4*)&a[4] = *(const float4*)&As[cb][k][64 + ty * 4];
            *(float4*)&b[0] = *(const float4*)&Bs[cb][k][tx * 4];
            *(float4*)&b[4] = *(const float4*)&Bs[cb][k][64 + tx * 4];
#pragma unroll
            for (int i = 0; i < 8; i++)
#pragma unroll
                for (int j = 0; j < 8; j++)
                    acc[i][j] = fmaf(a[i], b[j], acc[i][j]);
        }
        if (t + 1 < NT) {
            As[nb][acol + 0][arow] = ga.x;
            As[nb][acol + 1][arow] = ga.y;
            As[nb][acol + 2][arow] = ga.z;
            As[nb][acol + 3][arow] = ga.w;
            *(float4*)&Bs[nb][brow][bcol] = gb;
        }
        __syncthreads();
    }

#pragma unroll
    for (int i = 0; i < 8; i++) {
        const int ml = (i < 4) ? (ty * 4 + i) : (64 + ty * 4 + (i - 4));
        const int m = m0 + ml;
#pragma unroll
        for (int jj = 0; jj < 2; jj++) {
            const int n = n0 + (jj ? (64 + tx * 4) : (tx * 4));
            float4 v;
            v.x = acc[i][jj * 4 + 0] + bo[n + 0];
            v.y = acc[i][jj * 4 + 1] + bo[n + 1];
            v.z = acc[i][jj * 4 + 2] + bo[n + 2];
            v.w = acc[i][jj * 4 + 3] + bo[n + 3];
            *(float4*)&out[(size_t)m * N + n] = v;
        }
    }
}

// ---------------------------------------------------------------------------
// Flash attention: per (b, h, q-tile of 64). KV tiles of 64. Online softmax.
// grid = (S/64, H, B), 256 threads as 16x16, each thread 4x4 scores / 4x4 ctx.
// smem: Qt[d][r], Kt[d][c] (transposed for conflict-free LDS.128),
//       Vs[c][vd], Ps[r][c]. Each [64][LDP].
// ---------------------------------------------------------------------------
__global__ __launch_bounds__(256) void flash_kernel()
{
    extern __shared__ float sm[];
    float* Qt = sm;
    float* Kt = sm + 64 * LDP;
    float* Vs = sm + 2 * 64 * LDP;
    float* Ps = sm + 3 * 64 * LDP;

    const int tid = threadIdx.x;
    const int s0 = blockIdx.x * 64;
    const int h = blockIdx.y;
    const int b = blockIdx.z;
    const int bh = b * HEADS + h;

    const float* __restrict__ qg = g_q + ((size_t)bh * SEQ + s0) * HDIM;

    // Load Q tile transposed: Qt[d][r]
#pragma unroll
    for (int it = 0; it < 4; it++) {
        const int idx = tid + it * 256;           // 0..1023 float4s
        const int r = idx >> 4;
        const int c4 = (idx & 15) << 2;
        float4 v = *(const float4*)(qg + r * HDIM + c4);
        Qt[(c4 + 0) * LDP + r] = v.x;
        Qt[(c4 + 1) * LDP + r] = v.y;
        Qt[(c4 + 2) * LDP + r] = v.z;
        Qt[(c4 + 3) * LDP + r] = v.w;
    }

    const int tx = tid & 15;
    const int ty = tid >> 4;

    float m_i[4], l_i[4], acc[4][4];
#pragma unroll
    for (int i = 0; i < 4; i++) {
        m_i[i] = -1e30f;
        l_i[i] = 0.f;
#pragma unroll
        for (int j = 0; j < 4; j++) acc[i][j] = 0.f;
    }

    const float scale = 0.125f;  // 1/sqrt(64)

    for (int kt = 0; kt < SEQ / 64; kt++) {
        const float* __restrict__ kg = g_k + ((size_t)bh * SEQ + kt * 64) * HDIM;
        const float* __restrict__ vg = g_v + ((size_t)bh * SEQ + kt * 64) * HDIM;

        // Load K transposed, V direct
#pragma unroll
        for (int it = 0; it < 4; it++) {
            const int idx = tid + it * 256;
            const int r = idx >> 4;
            const int c4 = (idx & 15) << 2;
            float4 kvv = *(const float4*)(kg + r * HDIM + c4);
            Kt[(c4 + 0) * LDP + r] = kvv.x;
            Kt[(c4 + 1) * LDP + r] = kvv.y;
            Kt[(c4 + 2) * LDP + r] = kvv.z;
            Kt[(c4 + 3) * LDP + r] = kvv.w;
            float4 vv = *(const float4*)(vg + r * HDIM + c4);
            *(float4*)&Vs[r * LDP + c4] = vv;
        }
        __syncthreads();

        // S = Q K^T  (4x4 per thread)
        float s[4][4];
#pragma unroll
        for (int i = 0; i < 4; i++)
#pragma unroll
            for (int j = 0; j < 4; j++) s[i][j] = 0.f;

#pragma unroll 16
        for (int d = 0; d < 64; d++) {
            float4 qa = *(const float4*)&Qt[d * LDP + ty * 4];
            float4 kb = *(const float4*)&Kt[d * LDP + tx * 4];
            float aa[4] = {qa.x, qa.y, qa.z, qa.w};
            float bb[4] = {kb.x, kb.y, kb.z, kb.w};
#pragma unroll
            for (int i = 0; i < 4; i++)
#pragma unroll
                for (int j = 0; j < 4; j++)
                    s[i][j] = fmaf(aa[i], bb[j], s[i][j]);
        }

        // Online softmax for the 4 rows this thread co-owns
#pragma unroll
        for (int i = 0; i < 4; i++) {
            float rmax = s[i][0] * scale;
#pragma unroll
            for (int j = 1; j < 4; j++) rmax = fmaxf(rmax, s[i][j] * scale);
#pragma unroll
            for (int off = 8; off; off >>= 1)
                rmax = fmaxf(rmax, __shfl_xor_sync(0xffffffffu, rmax, off, 16));
            const float m_new = fmaxf(m_i[i], rmax);
            const float alpha = __expf(m_i[i] - m_new);
            float rs = 0.f;
#pragma unroll
            for (int j = 0; j < 4; j++) {
                float p = __expf(fmaf(s[i][j], scale, -m_new));
                s[i][j] = p;
                rs += p;
            }
#pragma unroll
            for (int off = 8; off; off >>= 1)
                rs += __shfl_xor_sync(0xffffffffu, rs, off, 16);
            l_i[i] = l_i[i] * alpha + rs;
            m_i[i] = m_new;
#pragma unroll
            for (int j = 0; j < 4; j++) acc[i][j] *= alpha;
        }

        // Store P tile
#pragma unroll
        for (int i = 0; i < 4; i++) {
            float4 pv = make_float4(s[i][0], s[i][1], s[i][2], s[i][3]);
            *(float4*)&Ps[(ty * 4 + i) * LDP + tx * 4] = pv;
        }
        __syncthreads();

        // ctx += P @ V
#pragma unroll 16
        for (int k = 0; k < 64; k++) {
            float4 vv = *(const float4*)&Vs[k * LDP + tx * 4];
            float vb[4] = {vv.x, vv.y, vv.z, vv.w};
            float p0 = Ps[(ty * 4 + 0) * LDP + k];
            float p1 = Ps[(ty * 4 + 1) * LDP + k];
            float p2 = Ps[(ty * 4 + 2) * LDP + k];
            float p3 = Ps[(ty * 4 + 3) * LDP + k];
#pragma unroll
            for (int j = 0; j < 4; j++) {
                acc[0][j] = fmaf(p0, vb[j], acc[0][j]);
                acc[1][j] = fmaf(p1, vb[j], acc[1][j]);
                acc[2][j] = fmaf(p2, vb[j], acc[2][j]);
                acc[3][j] = fmaf(p3, vb[j], acc[3][j]);
            }
        }
        __syncthreads();
    }

    // Normalize and write ctx as [B, S, H*hd]
#pragma unroll
    for (int i = 0; i < 4; i++) {
        const int r = s0 + ty * 4 + i;
        const float inv = 1.0f / l_i[i];
        float4 o = make_float4(acc[i][0] * inv, acc[i][1] * inv,
                               acc[i][2] * inv, acc[i][3] * inv);
        *(float4*)&g_ctx[((size_t)b * SEQ + r) * DMODEL + h * HDIM + tx * 4] = o;
    }
}

// ---------------------------------------------------------------------------
extern "C" void kernel_launch(void* const* d_in, const int* in_sizes, int n_in,
                              void* d_out, int out_size)
{
    const float* x  = (const float*)d_in[0];
    const float* Wq = (const float*)d_in[1];
    const float* Wk = (const float*)d_in[2];
    const float* Wv = (const float*)d_in[3];
    const float* Wo = (const float*)d_in[4];
    const float* bo = (const float*)d_in[5];
    float* out = (float*)d_out;

    const int flash_smem = 4 * 64 * LDP * sizeof(float);  // 69632 B
    cudaFuncSetAttribute(flash_kernel, cudaFuncAttributeMaxDynamicSharedMemorySize,
                         flash_smem);

    dim3 gemm_grid(DMODEL / 128, MTOT / 128, 3);
    qkv_gemm_kernel<<<gemm_grid, 256>>>(x, Wq, Wk, Wv);

    dim3 flash_grid(SEQ / 64, HEADS, BATCH);
    flash_kernel<<<flash_grid, 256, flash_smem>>>();

    dim3 oproj_grid(DMODEL / 128, MTOT / 128, 1);
    oproj_gemm_kernel<<<oproj_grid, 256>>>(Wo, bo, out);
}

// round 8
// speedup vs baseline: 1.0133x; 1.0133x over previous
#include <cuda_runtime.h>
#include <mma.h>

using namespace nvcuda;

// Problem constants (fixed shapes from reference)
#define BATCH   4
#define SEQ     2048
#define DMODEL  1024
#define HEADS   16
#define HDIM    64
#define MTOT    (BATCH*SEQ)      // 8192

// Scratch (no cudaMalloc allowed)
__device__ float g_q[MTOT * DMODEL];
__device__ float g_k[MTOT * DMODEL];
__device__ float g_v[MTOT * DMODEL];
__device__ float g_ctx[MTOT * DMODEL];

using FragA  = wmma::fragment<wmma::matrix_a, 16, 16, 8, wmma::precision::tf32, wmma::row_major>;
using FragBr = wmma::fragment<wmma::matrix_b, 16, 16, 8, wmma::precision::tf32, wmma::row_major>;
using FragBc = wmma::fragment<wmma::matrix_b, 16, 16, 8, wmma::precision::tf32, wmma::col_major>;
using FragC  = wmma::fragment<wmma::accumulator, 16, 16, 8, float>;

// ---------------------------------------------------------------------------
// TF32 wmma GEMM: C[8192,1024] = A[8192,1024] @ W[1024,1024]
// Block 128x128, 256 threads = 8 warps (2x4), warp tile 64x32, k-chunk 16,
// double-buffered plain row-major smem tiles.
// MODE 0: A = x (param), QKV permuted store out[b,h,s,d] (blockIdx.z selects).
// MODE 1: A = g_ctx (device global, NEVER passed from host), plain store.
// ---------------------------------------------------------------------------
#define LDA 20
#define LDB 132

template<int MODE>
__global__ __launch_bounds__(256) void gemm_wmma(
    const float* __restrict__ Ain,
    const float* __restrict__ W0, const float* __restrict__ W1,
    const float* __restrict__ W2,
    float* __restrict__ outp)
{
    __shared__ float As[2][128 * LDA];
    __shared__ float Bs[2][16 * LDB];

    // IMPORTANT: __device__ globals must be referenced in DEVICE code only.
    // Passing g_ctx as a host-side kernel argument yields an invalid pointer.
    const float* __restrict__ A = (MODE == 0) ? Ain : g_ctx;

    const float* __restrict__ W;
    float* __restrict__ out;
    if (MODE == 0) {
        W   = (blockIdx.z == 0) ? W0 : (blockIdx.z == 1) ? W1 : W2;
        out = (blockIdx.z == 0) ? g_q : (blockIdx.z == 1) ? g_k : g_v;
    } else {
        W = W0; out = outp;
    }

    const int tid = threadIdx.x;
    const int w   = tid >> 5;
    const int wm  = w >> 2;       // 0..1
    const int wn  = w & 3;        // 0..3
    const int m0  = blockIdx.y * 128;
    const int n0  = blockIdx.x * 128;

    // global load indexing (fixed per thread)
    const int a_row = tid >> 1;            // 0..127
    const int a_c8  = (tid & 1) << 3;      // 0 or 8
    const float* Ag = A + (size_t)(m0 + a_row) * DMODEL + a_c8;

    const int b_row = tid >> 4;            // 0..15
    const int b_c8  = (tid & 15) << 3;     // 0..120
    const float* Wg = W + (size_t)b_row * DMODEL + n0 + b_c8;

    // prime stage 0
    {
        float4 a0 = *(const float4*)(Ag);
        float4 a1 = *(const float4*)(Ag + 4);
        *(float4*)&As[0][a_row * LDA + a_c8]     = a0;
        *(float4*)&As[0][a_row * LDA + a_c8 + 4] = a1;
        float4 b0 = *(const float4*)(Wg);
        float4 b1 = *(const float4*)(Wg + 4);
        *(float4*)&Bs[0][b_row * LDB + b_c8]     = b0;
        *(float4*)&Bs[0][b_row * LDB + b_c8 + 4] = b1;
    }
    __syncthreads();

    FragC c[4][2];
#pragma unroll
    for (int mt = 0; mt < 4; mt++)
#pragma unroll
        for (int nt = 0; nt < 2; nt++)
            wmma::fill_fragment(c[mt][nt], 0.0f);

    const int NT = DMODEL / 16;   // 64 chunks
    for (int t = 0; t < NT; t++) {
        const int cur = t & 1;
        float4 ga0, ga1, gb0, gb1;
        if (t + 1 < NT) {
            const int k0 = (t + 1) * 16;
            ga0 = *(const float4*)(Ag + k0);
            ga1 = *(const float4*)(Ag + k0 + 4);
            gb0 = *(const float4*)(Wg + (size_t)k0 * DMODEL);
            gb1 = *(const float4*)(Wg + (size_t)k0 * DMODEL + 4);
        }

#pragma unroll
        for (int ks = 0; ks < 2; ks++) {
            FragA af[4];
            FragBr bf[2];
#pragma unroll
            for (int mt = 0; mt < 4; mt++) {
                wmma::load_matrix_sync(af[mt], &As[cur][(wm * 64 + mt * 16) * LDA + ks * 8], LDA);
#pragma unroll
                for (int e = 0; e < af[mt].num_elements; e++)
                    af[mt].x[e] = wmma::__float_to_tf32(af[mt].x[e]);
            }
#pragma unroll
            for (int nt = 0; nt < 2; nt++) {
                wmma::load_matrix_sync(bf[nt], &Bs[cur][ks * 8 * LDB + wn * 32 + nt * 16], LDB);
#pragma unroll
                for (int e = 0; e < bf[nt].num_elements; e++)
                    bf[nt].x[e] = wmma::__float_to_tf32(bf[nt].x[e]);
            }
#pragma unroll
            for (int mt = 0; mt < 4; mt++)
#pragma unroll
                for (int nt = 0; nt < 2; nt++)
                    wmma::mma_sync(c[mt][nt], af[mt], bf[nt], c[mt][nt]);
        }

        if (t + 1 < NT) {
            const int nxt = (t + 1) & 1;
            *(float4*)&As[nxt][a_row * LDA + a_c8]     = ga0;
            *(float4*)&As[nxt][a_row * LDA + a_c8 + 4] = ga1;
            *(float4*)&Bs[nxt][b_row * LDB + b_c8]     = gb0;
            *(float4*)&Bs[nxt][b_row * LDB + b_c8 + 4] = gb1;
        }
        __syncthreads();
    }

    // epilogue: direct wmma stores (16x16 tiles never cross head/batch bounds)
#pragma unroll
    for (int mt = 0; mt < 4; mt++) {
#pragma unroll
        for (int nt = 0; nt < 2; nt++) {
            const int mrow = m0 + wm * 64 + mt * 16;
            const int ncol = n0 + wn * 32 + nt * 16;
            if (MODE == 0) {
                const int bb = mrow >> 11, ss = mrow & (SEQ - 1);
                const int h  = ncol >> 6,  d  = ncol & 63;
                float* dst = out + ((size_t)((bb << 4) + h) * SEQ + ss) * HDIM + d;
                wmma::store_matrix_sync(dst, c[mt][nt], HDIM, wmma::mem_row_major);
            } else {
                wmma::store_matrix_sync(out + (size_t)mrow * DMODEL + ncol,
                                        c[mt][nt], DMODEL, wmma::mem_row_major);
            }
        }
    }
}

// ---------------------------------------------------------------------------
// bias add: out[m][n] += bo[n]  (bo is zeros in this dataset; kept for rigor)
// ---------------------------------------------------------------------------
__global__ __launch_bounds__(256) void bias_add(float* __restrict__ out,
                                                const float* __restrict__ bo)
{
    const int i = blockIdx.x * 256 + threadIdx.x;   // float4 index
    const int j = (i << 2) & (DMODEL - 1);
    float4 v = ((float4*)out)[i];
    v.x += bo[j]; v.y += bo[j + 1]; v.z += bo[j + 2]; v.w += bo[j + 3];
    ((float4*)out)[i] = v;
}

// ---------------------------------------------------------------------------
// TF32 wmma flash attention.
// Block = (q-tile 128, head, batch), 256 threads = 8 warps.
// Warp w owns S/O rows [16w, 16w+16). KV tiles of 64. Online softmax with
// smem round-trips for S/P/O-delta (wmma fragment mapping is opaque).
// smem (floats, stride 68): Qs 128x68 | Ks 64x68 | Vs 64x68 | Ss 128x68 | Cs 128x68
// total 512*68*4 = 139264 B (dynamic).
// ---------------------------------------------------------------------------
#define LDS 68

__global__ __launch_bounds__(256) void flash_wmma()
{
    extern __shared__ float sm[];
    float* Qs = sm;
    float* Ks = Qs + 128 * LDS;
    float* Vs = Ks + 64 * LDS;
    float* Ss = Vs + 64 * LDS;
    float* Cs = Ss + 128 * LDS;

    const int tid = threadIdx.x;
    const int w   = tid >> 5;
    const int s0  = blockIdx.x * 128;
    const int h   = blockIdx.y;
    const int b   = blockIdx.z;
    const int bh  = b * HEADS + h;

    const float* __restrict__ qg = g_q + ((size_t)bh * SEQ + s0) * HDIM;

    // load Q tile (128x64) and zero ctx
#pragma unroll
    for (int i = 0; i < 8; i++) {
        const int idx = tid + 256 * i;
        const int r = idx >> 4, c4 = (idx & 15) << 2;
        *(float4*)&Qs[r * LDS + c4] = *(const float4*)(qg + r * HDIM + c4);
    }
#pragma unroll
    for (int i = 0; i < 34; i++)
        Cs[tid + 256 * i] = 0.0f;
    __syncthreads();

    const int row  = tid >> 1;          // 0..127 (softmax row owned by this thread)
    const int cofs = (tid & 1) * 32;    // half-row offset
    float m_i = -1e30f, l_i = 0.0f;
    const float scale = 0.125f;         // 1/sqrt(64)

    for (int kt = 0; kt < SEQ / 64; kt++) {
        const float* __restrict__ kg = g_k + ((size_t)bh * SEQ + kt * 64) * HDIM;
        const float* __restrict__ vg = g_v + ((size_t)bh * SEQ + kt * 64) * HDIM;

        __syncthreads();   // all warps done with previous Ks/Vs
#pragma unroll
        for (int i = 0; i < 4; i++) {
            const int idx = tid + 256 * i;
            const int r = idx >> 4, c4 = (idx & 15) << 2;
            *(float4*)&Ks[r * LDS + c4] = *(const float4*)(kg + r * HDIM + c4);
            *(float4*)&Vs[r * LDS + c4] = *(const float4*)(vg + r * HDIM + c4);
        }
        __syncthreads();

        // ---- S = Q K^T : warp strip 16 x 64 ----
        {
            FragC sc[4];
#pragma unroll
            for (int nt = 0; nt < 4; nt++) wmma::fill_fragment(sc[nt], 0.0f);
#pragma unroll
            for (int ks = 0; ks < 8; ks++) {
                FragA qa;
                wmma::load_matrix_sync(qa, &Qs[(w * 16) * LDS + ks * 8], LDS);
#pragma unroll
                for (int e = 0; e < qa.num_elements; e++)
                    qa.x[e] = wmma::__float_to_tf32(qa.x[e]);
#pragma unroll
                for (int nt = 0; nt < 4; nt++) {
                    FragBc kb;   // B(k=d, n=sk) col-major == K row-major
                    wmma::load_matrix_sync(kb, &Ks[(nt * 16) * LDS + ks * 8], LDS);
#pragma unroll
                    for (int e = 0; e < kb.num_elements; e++)
                        kb.x[e] = wmma::__float_to_tf32(kb.x[e]);
                    wmma::mma_sync(sc[nt], qa, kb, sc[nt]);
                }
            }
#pragma unroll
            for (int nt = 0; nt < 4; nt++)
                wmma::store_matrix_sync(&Ss[(w * 16) * LDS + nt * 16], sc[nt],
                                        LDS, wmma::mem_row_major);
        }
        __syncwarp();   // S strip is warp-local; make stores visible in-warp

        // ---- online softmax on this thread's half-row ----
        float alpha;
        {
            float* srow = &Ss[row * LDS + cofs];
            float mx = -1e30f;
#pragma unroll
            for (int j = 0; j < 32; j++) mx = fmaxf(mx, srow[j]);
            mx = fmaxf(mx, __shfl_xor_sync(0xffffffffu, mx, 1));
            mx *= scale;
            const float m_new = fmaxf(m_i, mx);
            alpha = __expf(m_i - m_new);
            float sum = 0.0f;
#pragma unroll
            for (int j = 0; j < 32; j++) {
                const float p = __expf(fmaf(srow[j], scale, -m_new));
                srow[j] = p;
                sum += p;
            }
            sum += __shfl_xor_sync(0xffffffffu, sum, 1);
            l_i = l_i * alpha + sum;
            m_i = m_new;
        }
        __syncwarp();   // P strip visible in-warp

        // ---- O_delta = P @ V : warp strip 16 x 64 ----
        {
            FragC oc[4];
#pragma unroll
            for (int nt = 0; nt < 4; nt++) wmma::fill_fragment(oc[nt], 0.0f);
#pragma unroll
            for (int ks = 0; ks < 8; ks++) {
                FragA pa;
                wmma::load_matrix_sync(pa, &Ss[(w * 16) * LDS + ks * 8], LDS);
#pragma unroll
                for (int e = 0; e < pa.num_elements; e++)
                    pa.x[e] = wmma::__float_to_tf32(pa.x[e]);
#pragma unroll
                for (int nt = 0; nt < 4; nt++) {
                    FragBr vb;   // B(k=sk, n=d) row-major == V row-major
                    wmma::load_matrix_sync(vb, &Vs[(ks * 8) * LDS + nt * 16], LDS);
#pragma unroll
                    for (int e = 0; e < vb.num_elements; e++)
                        vb.x[e] = wmma::__float_to_tf32(vb.x[e]);
                    wmma::mma_sync(oc[nt], pa, vb, oc[nt]);
                }
            }
            // all P loads done (program order) -> reuse Ss strip for O_delta
#pragma unroll
            for (int nt = 0; nt < 4; nt++)
                wmma::store_matrix_sync(&Ss[(w * 16) * LDS + nt * 16], oc[nt],
                                        LDS, wmma::mem_row_major);
        }
        __syncwarp();

        // ---- ctx = ctx*alpha + O_delta on this thread's half-row ----
        {
            float* crow = &Cs[row * LDS + cofs];
            const float* orow = &Ss[row * LDS + cofs];
#pragma unroll
            for (int j = 0; j < 32; j++)
                crow[j] = fmaf(crow[j], alpha, orow[j]);
        }
    }

    // ---- normalize, write ctx as [B, S, H*hd] ----
    const float inv = 1.0f / l_i;
    float* dst = &g_ctx[((size_t)b * SEQ + s0 + row) * DMODEL + h * HDIM + cofs];
    const float* crow = &Cs[row * LDS + cofs];
#pragma unroll
    for (int j4 = 0; j4 < 8; j4++) {
        float4 v = *(const float4*)&crow[j4 * 4];
        v.x *= inv; v.y *= inv; v.z *= inv; v.w *= inv;
        *(float4*)&dst[j4 * 4] = v;
    }
}

// ---------------------------------------------------------------------------
extern "C" void kernel_launch(void* const* d_in, const int* in_sizes, int n_in,
                              void* d_out, int out_size)
{
    const float* x  = (const float*)d_in[0];
    const float* Wq = (const float*)d_in[1];
    const float* Wk = (const float*)d_in[2];
    const float* Wv = (const float*)d_in[3];
    const float* Wo = (const float*)d_in[4];
    const float* bo = (const float*)d_in[5];
    float* out = (float*)d_out;

    const int flash_smem = 512 * LDS * sizeof(float);   // 139264 B
    cudaFuncSetAttribute(flash_wmma, cudaFuncAttributeMaxDynamicSharedMemorySize,
                         flash_smem);

    dim3 qkv_grid(DMODEL / 128, MTOT / 128, 3);
    gemm_wmma<0><<<qkv_grid, 256>>>(x, Wq, Wk, Wv, nullptr);

    dim3 flash_grid(SEQ / 128, HEADS, BATCH);
    flash_wmma<<<flash_grid, 256, flash_smem>>>();

    dim3 oproj_grid(DMODEL / 128, MTOT / 128, 1);
    // A operand (g_ctx) is bound INSIDE device code via MODE==1; the first
    // argument is unused there. Never pass a __device__ symbol from host.
    gemm_wmma<1><<<oproj_grid, 256>>>(nullptr, Wo, nullptr, nullptr, out);

    bias_add<<<(MTOT * DMODEL / 4) / 256, 256>>>(out, bo);
}

// round 9
// speedup vs baseline: 2.4741x; 2.4416x over previous
#include <cuda_runtime.h>
#include <mma.h>
#include <cstdint>

// Problem constants (fixed shapes from reference)
#define BATCH   4
#define SEQ     2048
#define DMODEL  1024
#define HEADS   16
#define HDIM    64
#define MTOT    (BATCH*SEQ)      // 8192

// Scratch (no cudaMalloc allowed)
__device__ float g_q[MTOT * DMODEL];
__device__ float g_k[MTOT * DMODEL];
__device__ float g_v[MTOT * DMODEL];
__device__ float g_ctx[MTOT * DMODEL];

// tf32 round helper (compiler intrinsic — proven lmem-safe in round 8)
__device__ __forceinline__ float tf32r(float x) {
    return nvcuda::wmma::__float_to_tf32(x);
}
__device__ __forceinline__ uint32_t fu(float x) { return __float_as_uint(x); }

// mma.sync m16n8k8 tf32 as a MACRO: operands expand textually at the call
// site (constant array indices stay in registers). Function-parameter
// binding of asm operands caused the 128MiB local-memory pool in R3-5.
#define MMA_TF32(d0,d1,d2,d3,a0,a1,a2,a3,b0,b1)                          \
    asm volatile(                                                        \
        "mma.sync.aligned.m16n8k8.row.col.f32.tf32.tf32.f32 "            \
        "{%0,%1,%2,%3}, {%4,%5,%6,%7}, {%8,%9}, {%0,%1,%2,%3};\n"        \
        : "+f"(d0), "+f"(d1), "+f"(d2), "+f"(d3)                         \
        : "r"(a0), "r"(a1), "r"(a2), "r"(a3), "r"(b0), "r"(b1))

// ---------------------------------------------------------------------------
// TF32 GEMM: C[8192,1024] = A @ W (+bias in MODE 1)
// Block 128x128, 256 threads = 8 warps (2x4), warp tile 64x32, k-chunk 16,
// double-buffered padded row-major smem holding pre-converted tf32 values.
// Fragment gathers are conflict-free scalar LDS:
//   A-type (row*LDA + t):  LDA=20  -> banks g*20+t all distinct mod 32
//   B-type (t*LDB + g):    LDB=136 -> banks t*8+g  all distinct mod 32
// PTX m16n8k8 layouts (documented): A a0=(g,t) a1=(g+8,t) a2=(g,t+4) a3=(g+8,t+4)
// B b0=(k=t,n=g) b1=(k=t+4,n=g);  C c0=(g,2t) c1=(g,2t+1) c2=(g+8,2t) c3=(g+8,2t+1)
// ---------------------------------------------------------------------------
#define LDA 20
#define LDB 136

template<int MODE>
__global__ __launch_bounds__(256) void gemm_mma(
    const float* __restrict__ Ain,
    const float* __restrict__ W0, const float* __restrict__ W1,
    const float* __restrict__ W2,
    const float* __restrict__ bias, float* __restrict__ outp)
{
    __shared__ float As[2][128 * LDA];
    __shared__ float Bs[2][16 * LDB];

    // __device__ globals referenced in DEVICE code only (host symbol is invalid)
    const float* __restrict__ A = (MODE == 0) ? Ain : g_ctx;
    const float* __restrict__ W;
    float* __restrict__ out;
    if (MODE == 0) {
        W   = (blockIdx.z == 0) ? W0 : (blockIdx.z == 1) ? W1 : W2;
        out = (blockIdx.z == 0) ? g_q : (blockIdx.z == 1) ? g_k : g_v;
    } else {
        W = W0; out = outp;
    }

    const int tid  = threadIdx.x;
    const int lane = tid & 31;
    const int wq   = tid >> 5;
    const int wm   = wq >> 2;       // 0..1
    const int wn   = wq & 3;        // 0..3
    const int g    = lane >> 2;     // 0..7
    const int t    = lane & 3;      // 0..3
    const int m0   = blockIdx.y * 128;
    const int n0   = blockIdx.x * 128;

    const int a_row = tid >> 1;             // 0..127
    const int a_c8  = (tid & 1) << 3;       // 0 or 8
    const float* Ag = A + (size_t)(m0 + a_row) * DMODEL + a_c8;

    const int b_row = tid >> 4;             // 0..15
    const int b_c8  = (tid & 15) << 3;      // 0..120
    const float* Wg = W + (size_t)b_row * DMODEL + n0 + b_c8;

    // prime stage 0 (convert to tf32 once, here)
    {
        float4 v0 = *(const float4*)(Ag);
        float4 v1 = *(const float4*)(Ag + 4);
        float* d = &As[0][a_row * LDA + a_c8];
        d[0]=tf32r(v0.x); d[1]=tf32r(v0.y); d[2]=tf32r(v0.z); d[3]=tf32r(v0.w);
        d[4]=tf32r(v1.x); d[5]=tf32r(v1.y); d[6]=tf32r(v1.z); d[7]=tf32r(v1.w);
        float4 w0 = *(const float4*)(Wg);
        float4 w1 = *(const float4*)(Wg + 4);
        float* e = &Bs[0][b_row * LDB + b_c8];
        e[0]=tf32r(w0.x); e[1]=tf32r(w0.y); e[2]=tf32r(w0.z); e[3]=tf32r(w0.w);
        e[4]=tf32r(w1.x); e[5]=tf32r(w1.y); e[6]=tf32r(w1.z); e[7]=tf32r(w1.w);
    }
    __syncthreads();

    float acc[4][4][4];
#pragma unroll
    for (int mt = 0; mt < 4; mt++)
#pragma unroll
        for (int nt = 0; nt < 4; nt++)
#pragma unroll
            for (int c = 0; c < 4; c++) acc[mt][nt][c] = 0.f;

    const int NT = DMODEL / 16;   // 64 stages
    for (int ts = 0; ts < NT; ts++) {
        const int cur = ts & 1;
        float4 ga0, ga1, gb0, gb1;
        if (ts + 1 < NT) {
            const int k0 = (ts + 1) * 16;
            ga0 = *(const float4*)(Ag + k0);
            ga1 = *(const float4*)(Ag + k0 + 4);
            gb0 = *(const float4*)(Wg + (size_t)k0 * DMODEL);
            gb1 = *(const float4*)(Wg + (size_t)k0 * DMODEL + 4);
        }

#pragma unroll
        for (int ks = 0; ks < 2; ks++) {
            uint32_t a0[4], a1[4], a2[4], a3[4];
#pragma unroll
            for (int mt = 0; mt < 4; mt++) {
                const int r0 = (wm * 64 + mt * 16 + g) * LDA + ks * 8;
                const int r1 = (wm * 64 + mt * 16 + g + 8) * LDA + ks * 8;
                a0[mt] = fu(As[cur][r0 + t]);
                a1[mt] = fu(As[cur][r1 + t]);
                a2[mt] = fu(As[cur][r0 + t + 4]);
                a3[mt] = fu(As[cur][r1 + t + 4]);
            }
            uint32_t b0[4], b1[4];
#pragma unroll
            for (int nt = 0; nt < 4; nt++) {
                const int col = wn * 32 + nt * 8 + g;
                b0[nt] = fu(Bs[cur][(ks * 8 + t) * LDB + col]);
                b1[nt] = fu(Bs[cur][(ks * 8 + t + 4) * LDB + col]);
            }
#pragma unroll
            for (int mt = 0; mt < 4; mt++)
#pragma unroll
                for (int nt = 0; nt < 4; nt++)
                    MMA_TF32(acc[mt][nt][0], acc[mt][nt][1], acc[mt][nt][2], acc[mt][nt][3],
                             a0[mt], a1[mt], a2[mt], a3[mt], b0[nt], b1[nt]);
        }

        if (ts + 1 < NT) {
            const int nxt = (ts + 1) & 1;
            float* d = &As[nxt][a_row * LDA + a_c8];
            d[0]=tf32r(ga0.x); d[1]=tf32r(ga0.y); d[2]=tf32r(ga0.z); d[3]=tf32r(ga0.w);
            d[4]=tf32r(ga1.x); d[5]=tf32r(ga1.y); d[6]=tf32r(ga1.z); d[7]=tf32r(ga1.w);
            float* e = &Bs[nxt][b_row * LDB + b_c8];
            e[0]=tf32r(gb0.x); e[1]=tf32r(gb0.y); e[2]=tf32r(gb0.z); e[3]=tf32r(gb0.w);
            e[4]=tf32r(gb1.x); e[5]=tf32r(gb1.y); e[6]=tf32r(gb1.z); e[7]=tf32r(gb1.w);
        }
        __syncthreads();
    }

    // epilogue: c0,c1 -> (row, 2t/2t+1), c2,c3 -> (row+8, ...)
#pragma unroll
    for (int mt = 0; mt < 4; mt++) {
#pragma unroll
        for (int nt = 0; nt < 4; nt++) {
            const int n  = n0 + wn * 32 + nt * 8 + 2 * t;
            const int mr = m0 + wm * 64 + mt * 16 + g;
            if (MODE == 0) {
                const int h = n >> 6, d = n & 63;
                const int bb = mr >> 11;
                {
                    const int ss = mr & (SEQ - 1);
                    float2 v = make_float2(acc[mt][nt][0], acc[mt][nt][1]);
                    *(float2*)&out[((size_t)((bb << 4) + h) * SEQ + ss) * HDIM + d] = v;
                }
                {
                    const int m2 = mr + 8;
                    const int bb2 = m2 >> 11, ss2 = m2 & (SEQ - 1);
                    float2 v = make_float2(acc[mt][nt][2], acc[mt][nt][3]);
                    *(float2*)&out[((size_t)((bb2 << 4) + h) * SEQ + ss2) * HDIM + d] = v;
                }
            } else {
                const float bv0 = bias[n], bv1 = bias[n + 1];
                float2 v0 = make_float2(acc[mt][nt][0] + bv0, acc[mt][nt][1] + bv1);
                float2 v1 = make_float2(acc[mt][nt][2] + bv0, acc[mt][nt][3] + bv1);
                *(float2*)&out[(size_t)mr * DMODEL + n] = v0;
                *(float2*)&out[(size_t)(mr + 8) * DMODEL + n] = v1;
            }
        }
    }
}

// ---------------------------------------------------------------------------
// TF32 register-resident flash attention.
// Block = (q-tile 64, head, batch), 128 threads = 4 warps; warp w owns rows
// [16w,16w+16). KV tiles of 64. Q fragments persistent in registers; softmax
// on C-fragment registers; P re-fragmented C->A via quad shuffles; O in regs.
// smem (tf32-rounded floats): Qs 64xLQ | Ks 64xLK | Vs 64xLV
// ---------------------------------------------------------------------------
#define LQ 68
#define LK 72
#define LV 72
#define FLASH_SMEM ((64*LQ + 64*LK + 64*LV) * 4)

__global__ __launch_bounds__(128) void flash_mma()
{
    extern __shared__ float sm[];
    float* Qs = sm;
    float* Ks = sm + 64 * LQ;
    float* Vs = sm + 64 * LQ + 64 * LK;

    const int tid  = threadIdx.x;
    const int lane = tid & 31;
    const int w    = tid >> 5;
    const int g    = lane >> 2;
    const int t    = lane & 3;
    const int s0   = blockIdx.x * 64;
    const int h    = blockIdx.y;
    const int b    = blockIdx.z;
    const int bh   = b * HEADS + h;

    const float* __restrict__ qg = g_q + ((size_t)bh * SEQ + s0) * HDIM;

    // stage Q (scale 1/8 folded in — exact power of 2, so tf32 rounding unchanged)
#pragma unroll
    for (int i = 0; i < 8; i++) {
        const int idx = tid + 128 * i;          // 0..1023
        const int r = idx >> 4, c4 = (idx & 15) << 2;
        float4 v = *(const float4*)(qg + r * HDIM + c4);
        float* d = &Qs[r * LQ + c4];
        d[0] = tf32r(v.x * 0.125f); d[1] = tf32r(v.y * 0.125f);
        d[2] = tf32r(v.z * 0.125f); d[3] = tf32r(v.w * 0.125f);
    }
    __syncthreads();

    // persistent Q fragments (8 k-chunks)
    uint32_t qa0[8], qa1[8], qa2[8], qa3[8];
    {
        const int r0 = (w * 16 + g) * LQ;
        const int r1 = (w * 16 + g + 8) * LQ;
#pragma unroll
        for (int kc = 0; kc < 8; kc++) {
            qa0[kc] = fu(Qs[r0 + kc * 8 + t]);
            qa1[kc] = fu(Qs[r1 + kc * 8 + t]);
            qa2[kc] = fu(Qs[r0 + kc * 8 + t + 4]);
            qa3[kc] = fu(Qs[r1 + kc * 8 + t + 4]);
        }
    }

    float o[8][4];
#pragma unroll
    for (int nt = 0; nt < 8; nt++)
#pragma unroll
        for (int c = 0; c < 4; c++) o[nt][c] = 0.f;
    float mx0 = -1e30f, mx1 = -1e30f, l0 = 0.f, l1 = 0.f;

    const int shA = (lane & 28) | (t >> 1);   // src lane for cols t (parity-selected)
    const int shB = shA + 2;                  // src lane for cols t+4

    for (int kt = 0; kt < SEQ / 64; kt++) {
        const float* __restrict__ kg = g_k + ((size_t)bh * SEQ + kt * 64) * HDIM;
        const float* __restrict__ vg = g_v + ((size_t)bh * SEQ + kt * 64) * HDIM;

        __syncthreads();   // previous Ks/Vs fully consumed
#pragma unroll
        for (int i = 0; i < 8; i++) {
            const int idx = tid + 128 * i;
            const int r = idx >> 4, c4 = (idx & 15) << 2;
            float4 kv = *(const float4*)(kg + r * HDIM + c4);
            float* dk = &Ks[r * LK + c4];
            dk[0]=tf32r(kv.x); dk[1]=tf32r(kv.y); dk[2]=tf32r(kv.z); dk[3]=tf32r(kv.w);
            float4 vv = *(const float4*)(vg + r * HDIM + c4);
            float* dv = &Vs[r * LV + c4];
            dv[0]=tf32r(vv.x); dv[1]=tf32r(vv.y); dv[2]=tf32r(vv.z); dv[3]=tf32r(vv.w);
        }
        __syncthreads();

        // ---- S = (Q/8) K^T : 8 n-tiles x 8 k-chunks ----
        float s[8][4];
#pragma unroll
        for (int nt = 0; nt < 8; nt++)
#pragma unroll
            for (int c = 0; c < 4; c++) s[nt][c] = 0.f;

#pragma unroll
        for (int kc = 0; kc < 8; kc++) {
#pragma unroll
            for (int nt = 0; nt < 8; nt++) {
                const int kr = (nt * 8 + g) * LK + kc * 8;
                uint32_t b0 = fu(Ks[kr + t]);
                uint32_t b1 = fu(Ks[kr + t + 4]);
                MMA_TF32(s[nt][0], s[nt][1], s[nt][2], s[nt][3],
                         qa0[kc], qa1[kc], qa2[kc], qa3[kc], b0, b1);
            }
        }

        // ---- online softmax on C-register rows (g: regs 0,1 | g+8: regs 2,3) ----
        float alpha0, alpha1;
        {
            float ma = -1e30f, mb = -1e30f;
#pragma unroll
            for (int nt = 0; nt < 8; nt++) {
                ma = fmaxf(ma, fmaxf(s[nt][0], s[nt][1]));
                mb = fmaxf(mb, fmaxf(s[nt][2], s[nt][3]));
            }
            ma = fmaxf(ma, __shfl_xor_sync(0xffffffffu, ma, 1));
            ma = fmaxf(ma, __shfl_xor_sync(0xffffffffu, ma, 2));
            mb = fmaxf(mb, __shfl_xor_sync(0xffffffffu, mb, 1));
            mb = fmaxf(mb, __shfl_xor_sync(0xffffffffu, mb, 2));
            const float n0m = fmaxf(mx0, ma);
            const float n1m = fmaxf(mx1, mb);
            alpha0 = __expf(mx0 - n0m);
            alpha1 = __expf(mx1 - n1m);
            mx0 = n0m; mx1 = n1m;
            float sa = 0.f, sb = 0.f;
#pragma unroll
            for (int nt = 0; nt < 8; nt++) {
                s[nt][0] = __expf(s[nt][0] - n0m);
                s[nt][1] = __expf(s[nt][1] - n0m);
                s[nt][2] = __expf(s[nt][2] - n1m);
                s[nt][3] = __expf(s[nt][3] - n1m);
                sa += s[nt][0] + s[nt][1];
                sb += s[nt][2] + s[nt][3];
            }
            sa += __shfl_xor_sync(0xffffffffu, sa, 1);
            sa += __shfl_xor_sync(0xffffffffu, sa, 2);
            sb += __shfl_xor_sync(0xffffffffu, sb, 1);
            sb += __shfl_xor_sync(0xffffffffu, sb, 2);
            l0 = l0 * alpha0 + sa;
            l1 = l1 * alpha1 + sb;
#pragma unroll
            for (int nt = 0; nt < 8; nt++) {
                o[nt][0] *= alpha0; o[nt][1] *= alpha0;
                o[nt][2] *= alpha1; o[nt][3] *= alpha1;
            }
        }

        // ---- O += P V : re-fragment P (C layout -> A layout) via quad shuffles ----
        // A-frag col c: held in C by lane (g*4 + c>>1), reg parity c&1.
#pragma unroll
        for (int kc = 0; kc < 8; kc++) {
            const float p00 = __shfl_sync(0xffffffffu, s[kc][0], shA);
            const float p01 = __shfl_sync(0xffffffffu, s[kc][1], shA);
            const float p10 = __shfl_sync(0xffffffffu, s[kc][2], shA);
            const float p11 = __shfl_sync(0xffffffffu, s[kc][3], shA);
            const float q00 = __shfl_sync(0xffffffffu, s[kc][0], shB);
            const float q01 = __shfl_sync(0xffffffffu, s[kc][1], shB);
            const float q10 = __shfl_sync(0xffffffffu, s[kc][2], shB);
            const float q11 = __shfl_sync(0xffffffffu, s[kc][3], shB);
            const uint32_t a0 = fu(tf32r((t & 1) ? p01 : p00));
            const uint32_t a1 = fu(tf32r((t & 1) ? p11 : p10));
            const uint32_t a2 = fu(tf32r((t & 1) ? q01 : q00));
            const uint32_t a3 = fu(tf32r((t & 1) ? q11 : q10));
#pragma unroll
            for (int nt = 0; nt < 8; nt++) {
                const int vr = (kc * 8 + t) * LV + nt * 8 + g;
                uint32_t b0 = fu(Vs[vr]);
                uint32_t b1 = fu(Vs[vr + 4 * LV]);
                MMA_TF32(o[nt][0], o[nt][1], o[nt][2], o[nt][3],
                         a0, a1, a2, a3, b0, b1);
            }
        }
    }

    // ---- normalize + write ctx [B, S, H*hd] ----
    const float inv0 = 1.0f / l0;
    const float inv1 = 1.0f / l1;
    const int row0 = s0 + w * 16 + g;
    float* dst0 = &g_ctx[((size_t)b * SEQ + row0) * DMODEL + h * HDIM];
    float* dst1 = dst0 + 8 * DMODEL;
#pragma unroll
    for (int nt = 0; nt < 8; nt++) {
        const int col = nt * 8 + 2 * t;
        *(float2*)&dst0[col] = make_float2(o[nt][0] * inv0, o[nt][1] * inv0);
        *(float2*)&dst1[col] = make_float2(o[nt][2] * inv1, o[nt][3] * inv1);
    }
}

// ---------------------------------------------------------------------------
extern "C" void kernel_launch(void* const* d_in, const int* in_sizes, int n_in,
                              void* d_out, int out_size)
{
    const float* x  = (const float*)d_in[0];
    const float* Wq = (const float*)d_in[1];
    const float* Wk = (const float*)d_in[2];
    const float* Wv = (const float*)d_in[3];
    const float* Wo = (const float*)d_in[4];
    const float* bo = (const float*)d_in[5];
    float* out = (float*)d_out;

    cudaFuncSetAttribute(flash_mma, cudaFuncAttributeMaxDynamicSharedMemorySize,
                         FLASH_SMEM);

    dim3 qkv_grid(DMODEL / 128, MTOT / 128, 3);
    gemm_mma<0><<<qkv_grid, 256>>>(x, Wq, Wk, Wv, nullptr, nullptr);

    dim3 flash_grid(SEQ / 64, HEADS, BATCH);
    flash_mma<<<flash_grid, 128, FLASH_SMEM>>>();

    dim3 oproj_grid(DMODEL / 128, MTOT / 128, 1);
    gemm_mma<1><<<oproj_grid, 256>>>(nullptr, Wo, nullptr, nullptr, bo, out);
}

// round 10
// speedup vs baseline: 3.2485x; 1.3130x over previous
#include <cuda_runtime.h>
#include <mma.h>
#include <cstdint>

// Problem constants (fixed shapes from reference)
#define BATCH   4
#define SEQ     2048
#define DMODEL  1024
#define HEADS   16
#define HDIM    64
#define MTOT    (BATCH*SEQ)      // 8192

// Scratch (no cudaMalloc allowed)
__device__ float g_q[MTOT * DMODEL];
__device__ float g_k[MTOT * DMODEL];
__device__ float g_v[MTOT * DMODEL];
__device__ float g_ctx[MTOT * DMODEL];

__device__ __forceinline__ float tf32r(float x) {
    return nvcuda::wmma::__float_to_tf32(x);
}
__device__ __forceinline__ uint32_t fu(float x) { return __float_as_uint(x); }

// mma.sync m16n8k8 tf32 as a MACRO (function-parameter operand binding caused
// the 128MiB local-memory pool in R3-5; macro expansion is proven safe).
#define MMA_TF32(d0,d1,d2,d3,a0,a1,a2,a3,b0,b1)                          \
    asm volatile(                                                        \
        "mma.sync.aligned.m16n8k8.row.col.f32.tf32.tf32.f32 "            \
        "{%0,%1,%2,%3}, {%4,%5,%6,%7}, {%8,%9}, {%0,%1,%2,%3};\n"        \
        : "+f"(d0), "+f"(d1), "+f"(d2), "+f"(d3)                         \
        : "r"(a0), "r"(a1), "r"(a2), "r"(a3), "r"(b0), "r"(b1))

// ---------------------------------------------------------------------------
// TF32 GEMM: C[8192,1024] = A @ W (+bias in MODE 1)
// Block tile 128x128, 128 threads = 4 warps (2x2), warp tile 64x64, k-stage 16,
// double-buffered padded row-major smem with pre-converted tf32 values.
// Conflict-free scalar gathers: LDA=20 (A-type), LDB=136 (B-type).
// ---------------------------------------------------------------------------
#define LDA 20
#define LDB 136

template<int MODE>
__global__ __launch_bounds__(128) void gemm_mma(
    const float* __restrict__ Ain,
    const float* __restrict__ W0, const float* __restrict__ W1,
    const float* __restrict__ W2,
    const float* __restrict__ bias, float* __restrict__ outp)
{
    __shared__ float As[2][128 * LDA];
    __shared__ float Bs[2][16 * LDB];

    // __device__ globals referenced in DEVICE code only
    const float* __restrict__ A = (MODE == 0) ? Ain : g_ctx;
    const float* __restrict__ W;
    float* __restrict__ out;
    if (MODE == 0) {
        W   = (blockIdx.z == 0) ? W0 : (blockIdx.z == 1) ? W1 : W2;
        out = (blockIdx.z == 0) ? g_q : (blockIdx.z == 1) ? g_k : g_v;
    } else {
        W = W0; out = outp;
    }

    const int tid  = threadIdx.x;
    const int lane = tid & 31;
    const int wq   = tid >> 5;      // 4 warps
    const int wm   = wq >> 1;       // 0..1
    const int wn   = wq & 1;        // 0..1
    const int g    = lane >> 2;     // 0..7
    const int t    = lane & 3;      // 0..3
    const int m0   = blockIdx.y * 128;
    const int n0   = blockIdx.x * 128;

    // global->smem staging: 2048 elems each, 128 threads, 4 float4 per thread
    // A: idx=tid+128i -> row=idx>>2 (0..127... wait 512 float4 -> r=idx>>2, c4=(idx&3)*4)
    const int a_r0 = tid >> 2;            // row base (0..31), rows r0+32*?
    const int a_c4 = (tid & 3) << 2;      // k col 0,4,8,12
    const int b_r0 = tid >> 5;            // 0..3
    const int b_c4 = (tid & 31) << 2;     // 0..124

    const float* Ag = A + (size_t)(m0 + a_r0) * DMODEL + a_c4;
    const float* Wg = W + (size_t)b_r0 * DMODEL + n0 + b_c4;

    // prime stage 0 (tf32 conversion happens once, at store)
#pragma unroll
    for (int i = 0; i < 4; i++) {
        float4 v = *(const float4*)(Ag + (size_t)(32 * i) * DMODEL);
        float* d = &As[0][(a_r0 + 32 * i) * LDA + a_c4];
        d[0]=tf32r(v.x); d[1]=tf32r(v.y); d[2]=tf32r(v.z); d[3]=tf32r(v.w);
        float4 u = *(const float4*)(Wg + (size_t)(4 * i) * DMODEL);
        float* e = &Bs[0][(b_r0 + 4 * i) * LDB + b_c4];
        e[0]=tf32r(u.x); e[1]=tf32r(u.y); e[2]=tf32r(u.z); e[3]=tf32r(u.w);
    }
    __syncthreads();

    float acc[4][8][4];
#pragma unroll
    for (int mt = 0; mt < 4; mt++)
#pragma unroll
        for (int nt = 0; nt < 8; nt++)
#pragma unroll
            for (int c = 0; c < 4; c++) acc[mt][nt][c] = 0.f;

    const int NT = DMODEL / 16;   // 64 stages
    for (int ts = 0; ts < NT; ts++) {
        const int cur = ts & 1;
        float4 ga[4], gb[4];
        if (ts + 1 < NT) {
            const int k0 = (ts + 1) * 16;
#pragma unroll
            for (int i = 0; i < 4; i++) {
                ga[i] = *(const float4*)(Ag + (size_t)(32 * i) * DMODEL + k0);
                gb[i] = *(const float4*)(Wg + (size_t)(k0 + 4 * i) * DMODEL);
            }
        }

#pragma unroll
        for (int ks = 0; ks < 2; ks++) {
            uint32_t a0[4], a1[4], a2[4], a3[4];
#pragma unroll
            for (int mt = 0; mt < 4; mt++) {
                const int r0 = (wm * 64 + mt * 16 + g) * LDA + ks * 8;
                const int r1 = (wm * 64 + mt * 16 + g + 8) * LDA + ks * 8;
                a0[mt] = fu(As[cur][r0 + t]);
                a1[mt] = fu(As[cur][r1 + t]);
                a2[mt] = fu(As[cur][r0 + t + 4]);
                a3[mt] = fu(As[cur][r1 + t + 4]);
            }
            uint32_t b0[8], b1[8];
#pragma unroll
            for (int nt = 0; nt < 8; nt++) {
                const int col = wn * 64 + nt * 8 + g;
                b0[nt] = fu(Bs[cur][(ks * 8 + t) * LDB + col]);
                b1[nt] = fu(Bs[cur][(ks * 8 + t + 4) * LDB + col]);
            }
#pragma unroll
            for (int mt = 0; mt < 4; mt++)
#pragma unroll
                for (int nt = 0; nt < 8; nt++)
                    MMA_TF32(acc[mt][nt][0], acc[mt][nt][1], acc[mt][nt][2], acc[mt][nt][3],
                             a0[mt], a1[mt], a2[mt], a3[mt], b0[nt], b1[nt]);
        }

        if (ts + 1 < NT) {
            const int nxt = (ts + 1) & 1;
#pragma unroll
            for (int i = 0; i < 4; i++) {
                float* d = &As[nxt][(a_r0 + 32 * i) * LDA + a_c4];
                d[0]=tf32r(ga[i].x); d[1]=tf32r(ga[i].y);
                d[2]=tf32r(ga[i].z); d[3]=tf32r(ga[i].w);
                float* e = &Bs[nxt][(b_r0 + 4 * i) * LDB + b_c4];
                e[0]=tf32r(gb[i].x); e[1]=tf32r(gb[i].y);
                e[2]=tf32r(gb[i].z); e[3]=tf32r(gb[i].w);
            }
        }
        __syncthreads();
    }

    // epilogue
#pragma unroll
    for (int mt = 0; mt < 4; mt++) {
#pragma unroll
        for (int nt = 0; nt < 8; nt++) {
            const int n  = n0 + wn * 64 + nt * 8 + 2 * t;
            const int mr = m0 + wm * 64 + mt * 16 + g;
            if (MODE == 0) {
                const int h = n >> 6, d = n & 63;
                {
                    const int bb = mr >> 11, ss = mr & (SEQ - 1);
                    float2 v = make_float2(acc[mt][nt][0], acc[mt][nt][1]);
                    *(float2*)&out[((size_t)((bb << 4) + h) * SEQ + ss) * HDIM + d] = v;
                }
                {
                    const int m2 = mr + 8;
                    const int bb2 = m2 >> 11, ss2 = m2 & (SEQ - 1);
                    float2 v = make_float2(acc[mt][nt][2], acc[mt][nt][3]);
                    *(float2*)&out[((size_t)((bb2 << 4) + h) * SEQ + ss2) * HDIM + d] = v;
                }
            } else {
                const float bv0 = bias[n], bv1 = bias[n + 1];
                float2 v0 = make_float2(acc[mt][nt][0] + bv0, acc[mt][nt][1] + bv1);
                float2 v1 = make_float2(acc[mt][nt][2] + bv0, acc[mt][nt][3] + bv1);
                *(float2*)&out[(size_t)mr * DMODEL + n] = v0;
                *(float2*)&out[(size_t)(mr + 8) * DMODEL + n] = v1;
            }
        }
    }
}

// ---------------------------------------------------------------------------
// TF32 register-resident flash attention, Q tile 128, 4 warps.
// Warp w owns rows [32w, 32w+32) as TWO m16 tiles -> K/V fragment loads are
// shared across both m-tiles (halves smem traffic per q-row vs round 9).
// KV tiles of 64. Softmax on C-fragment registers; P re-fragmented via quad
// shuffles; O accumulated in registers.
// smem: Qs 128xLQ | Ks 64xLK | Vs 64xLV  (tf32-rounded floats)
// ---------------------------------------------------------------------------
#define LQ 68
#define LK 72
#define LV 72
#define FLASH_SMEM ((128*LQ + 64*LK + 64*LV) * 4)

__global__ __launch_bounds__(128) void flash_mma()
{
    extern __shared__ float sm[];
    float* Qs = sm;
    float* Ks = sm + 128 * LQ;
    float* Vs = sm + 128 * LQ + 64 * LK;

    const int tid  = threadIdx.x;
    const int lane = tid & 31;
    const int w    = tid >> 5;
    const int g    = lane >> 2;
    const int t    = lane & 3;
    const int s0   = blockIdx.x * 128;
    const int h    = blockIdx.y;
    const int b    = blockIdx.z;
    const int bh   = b * HEADS + h;

    const float* __restrict__ qg = g_q + ((size_t)bh * SEQ + s0) * HDIM;

    // stage Q (scale 1/8 folded in — exact power of 2, tf32 rounding unchanged)
#pragma unroll
    for (int i = 0; i < 16; i++) {
        const int idx = tid + 128 * i;          // 0..2047 float4 slots
        const int r = idx >> 4, c4 = (idx & 15) << 2;
        float4 v = *(const float4*)(qg + r * HDIM + c4);
        float* d = &Qs[r * LQ + c4];
        d[0] = tf32r(v.x * 0.125f); d[1] = tf32r(v.y * 0.125f);
        d[2] = tf32r(v.z * 0.125f); d[3] = tf32r(v.w * 0.125f);
    }
    __syncthreads();

    float o[2][8][4];
#pragma unroll
    for (int mt = 0; mt < 2; mt++)
#pragma unroll
        for (int nt = 0; nt < 8; nt++)
#pragma unroll
            for (int c = 0; c < 4; c++) o[mt][nt][c] = 0.f;
    float mx[2][2], l[2][2];
#pragma unroll
    for (int mt = 0; mt < 2; mt++) {
        mx[mt][0] = mx[mt][1] = -1e30f;
        l[mt][0] = l[mt][1] = 0.f;
    }

    const int shA = (lane & 28) | (t >> 1);   // src lane for A-frag cols t
    const int shB = shA + 2;                  // src lane for cols t+4

    for (int kt = 0; kt < SEQ / 64; kt++) {
        const float* __restrict__ kg = g_k + ((size_t)bh * SEQ + kt * 64) * HDIM;
        const float* __restrict__ vg = g_v + ((size_t)bh * SEQ + kt * 64) * HDIM;

        __syncthreads();
#pragma unroll
        for (int i = 0; i < 8; i++) {
            const int idx = tid + 128 * i;
            const int r = idx >> 4, c4 = (idx & 15) << 2;
            float4 kv = *(const float4*)(kg + r * HDIM + c4);
            float* dk = &Ks[r * LK + c4];
            dk[0]=tf32r(kv.x); dk[1]=tf32r(kv.y); dk[2]=tf32r(kv.z); dk[3]=tf32r(kv.w);
            float4 vv = *(const float4*)(vg + r * HDIM + c4);
            float* dv = &Vs[r * LV + c4];
            dv[0]=tf32r(vv.x); dv[1]=tf32r(vv.y); dv[2]=tf32r(vv.z); dv[3]=tf32r(vv.w);
        }
        __syncthreads();

        // ---- S = (Q/8) K^T : 2 m-tiles x 8 n-tiles, K frags shared over mt ----
        float s[2][8][4];
#pragma unroll
        for (int mt = 0; mt < 2; mt++)
#pragma unroll
            for (int nt = 0; nt < 8; nt++)
#pragma unroll
                for (int c = 0; c < 4; c++) s[mt][nt][c] = 0.f;

#pragma unroll
        for (int kc = 0; kc < 8; kc++) {
            uint32_t qa0[2], qa1[2], qa2[2], qa3[2];
#pragma unroll
            for (int mt = 0; mt < 2; mt++) {
                const int r0 = (w * 32 + mt * 16 + g) * LQ + kc * 8;
                const int r1 = (w * 32 + mt * 16 + g + 8) * LQ + kc * 8;
                qa0[mt] = fu(Qs[r0 + t]);
                qa1[mt] = fu(Qs[r1 + t]);
                qa2[mt] = fu(Qs[r0 + t + 4]);
                qa3[mt] = fu(Qs[r1 + t + 4]);
            }
#pragma unroll
            for (int nt = 0; nt < 8; nt++) {
                const int kr = (nt * 8 + g) * LK + kc * 8;
                uint32_t b0 = fu(Ks[kr + t]);
                uint32_t b1 = fu(Ks[kr + t + 4]);
#pragma unroll
                for (int mt = 0; mt < 2; mt++)
                    MMA_TF32(s[mt][nt][0], s[mt][nt][1], s[mt][nt][2], s[mt][nt][3],
                             qa0[mt], qa1[mt], qa2[mt], qa3[mt], b0, b1);
            }
        }

        // ---- online softmax per m-tile (rows g: regs 0,1 | g+8: regs 2,3) ----
        float alpha[2][2];
#pragma unroll
        for (int mt = 0; mt < 2; mt++) {
            float ma = -1e30f, mb = -1e30f;
#pragma unroll
            for (int nt = 0; nt < 8; nt++) {
                ma = fmaxf(ma, fmaxf(s[mt][nt][0], s[mt][nt][1]));
                mb = fmaxf(mb, fmaxf(s[mt][nt][2], s[mt][nt][3]));
            }
            ma = fmaxf(ma, __shfl_xor_sync(0xffffffffu, ma, 1));
            ma = fmaxf(ma, __shfl_xor_sync(0xffffffffu, ma, 2));
            mb = fmaxf(mb, __shfl_xor_sync(0xffffffffu, mb, 1));
            mb = fmaxf(mb, __shfl_xor_sync(0xffffffffu, mb, 2));
            const float n0m = fmaxf(mx[mt][0], ma);
            const float n1m = fmaxf(mx[mt][1], mb);
            alpha[mt][0] = __expf(mx[mt][0] - n0m);
            alpha[mt][1] = __expf(mx[mt][1] - n1m);
            mx[mt][0] = n0m; mx[mt][1] = n1m;
            float sa = 0.f, sb = 0.f;
#pragma unroll
            for (int nt = 0; nt < 8; nt++) {
                s[mt][nt][0] = __expf(s[mt][nt][0] - n0m);
                s[mt][nt][1] = __expf(s[mt][nt][1] - n0m);
                s[mt][nt][2] = __expf(s[mt][nt][2] - n1m);
                s[mt][nt][3] = __expf(s[mt][nt][3] - n1m);
                sa += s[mt][nt][0] + s[mt][nt][1];
                sb += s[mt][nt][2] + s[mt][nt][3];
            }
            sa += __shfl_xor_sync(0xffffffffu, sa, 1);
            sa += __shfl_xor_sync(0xffffffffu, sa, 2);
            sb += __shfl_xor_sync(0xffffffffu, sb, 1);
            sb += __shfl_xor_sync(0xffffffffu, sb, 2);
            l[mt][0] = l[mt][0] * alpha[mt][0] + sa;
            l[mt][1] = l[mt][1] * alpha[mt][1] + sb;
#pragma unroll
            for (int nt = 0; nt < 8; nt++) {
                o[mt][nt][0] *= alpha[mt][0]; o[mt][nt][1] *= alpha[mt][0];
                o[mt][nt][2] *= alpha[mt][1]; o[mt][nt][3] *= alpha[mt][1];
            }
        }

        // ---- O += P V : re-fragment P via quad shuffles, V frags shared ----
#pragma unroll
        for (int kc = 0; kc < 8; kc++) {
            uint32_t a0[2], a1[2], a2[2], a3[2];
#pragma unroll
            for (int mt = 0; mt < 2; mt++) {
                const float p00 = __shfl_sync(0xffffffffu, s[mt][kc][0], shA);
                const float p01 = __shfl_sync(0xffffffffu, s[mt][kc][1], shA);
                const float p10 = __shfl_sync(0xffffffffu, s[mt][kc][2], shA);
                const float p11 = __shfl_sync(0xffffffffu, s[mt][kc][3], shA);
                const float q00 = __shfl_sync(0xffffffffu, s[mt][kc][0], shB);
                const float q01 = __shfl_sync(0xffffffffu, s[mt][kc][1], shB);
                const float q10 = __shfl_sync(0xffffffffu, s[mt][kc][2], shB);
                const float q11 = __shfl_sync(0xffffffffu, s[mt][kc][3], shB);
                a0[mt] = fu(tf32r((t & 1) ? p01 : p00));
                a1[mt] = fu(tf32r((t & 1) ? p11 : p10));
                a2[mt] = fu(tf32r((t & 1) ? q01 : q00));
                a3[mt] = fu(tf32r((t & 1) ? q11 : q10));
            }
#pragma unroll
            for (int nt = 0; nt < 8; nt++) {
                const int vr = (kc * 8 + t) * LV + nt * 8 + g;
                uint32_t b0 = fu(Vs[vr]);
                uint32_t b1 = fu(Vs[vr + 4 * LV]);
#pragma unroll
                for (int mt = 0; mt < 2; mt++)
                    MMA_TF32(o[mt][nt][0], o[mt][nt][1], o[mt][nt][2], o[mt][nt][3],
                             a0[mt], a1[mt], a2[mt], a3[mt], b0, b1);
            }
        }
    }

    // ---- normalize + write ctx [B, S, H*hd] ----
#pragma unroll
    for (int mt = 0; mt < 2; mt++) {
        const float inv0 = 1.0f / l[mt][0];
        const float inv1 = 1.0f / l[mt][1];
        const int row0 = s0 + w * 32 + mt * 16 + g;
        float* dst0 = &g_ctx[((size_t)b * SEQ + row0) * DMODEL + h * HDIM];
        float* dst1 = dst0 + 8 * DMODEL;
#pragma unroll
        for (int nt = 0; nt < 8; nt++) {
            const int col = nt * 8 + 2 * t;
            *(float2*)&dst0[col] = make_float2(o[mt][nt][0] * inv0, o[mt][nt][1] * inv0);
            *(float2*)&dst1[col] = make_float2(o[mt][nt][2] * inv1, o[mt][nt][3] * inv1);
        }
    }
}

// ---------------------------------------------------------------------------
extern "C" void kernel_launch(void* const* d_in, const int* in_sizes, int n_in,
                              void* d_out, int out_size)
{
    const float* x  = (const float*)d_in[0];
    const float* Wq = (const float*)d_in[1];
    const float* Wk = (const float*)d_in[2];
    const float* Wv = (const float*)d_in[3];
    const float* Wo = (const float*)d_in[4];
    const float* bo = (const float*)d_in[5];
    float* out = (float*)d_out;

    cudaFuncSetAttribute(flash_mma, cudaFuncAttributeMaxDynamicSharedMemorySize,
                         FLASH_SMEM);

    dim3 qkv_grid(DMODEL / 128, MTOT / 128, 3);
    gemm_mma<0><<<qkv_grid, 128>>>(x, Wq, Wk, Wv, nullptr, nullptr);

    dim3 flash_grid(SEQ / 128, HEADS, BATCH);
    flash_mma<<<flash_grid, 128, FLASH_SMEM>>>();

    dim3 oproj_grid(DMODEL / 128, MTOT / 128, 1);
    gemm_mma<1><<<oproj_grid, 128>>>(nullptr, Wo, nullptr, nullptr, bo, out);
}